// round 6
// baseline (speedup 1.0000x reference)
#include <cuda_runtime.h>
#include <cuda_bf16.h>
#include <cstdint>

// ---------------------------------------------------------------------------
// Scratch (device globals -- no allocation allowed)
// ---------------------------------------------------------------------------
__device__ float g_part[16777216];   // split-K partials (max: conv5 64*2*512*256)
__device__ float g_outA[16777216];   // ping  (2*512*128*128 max)
__device__ float g_outB[16777216];   // pong
__device__ float g_up  [16777216];   // upsampled out_prev
__device__ float g_q   [2097152];    // q maps (max 2*64*128*128)
__device__ float g_k   [2097152];    // hi-res k maps
__device__ float g_klo [524288];     // low-res k maps
__device__ float g_att [294912];     // attention 2*9*128*128 max

// ---------------------------------------------------------------------------
// conv5: 3x3 conv, IC=2048 -> OC=512, 16x16, pad 1.  Split-K partial sums.
// grid: (64 ic-chunks of 32, 8 oc-tiles of 64, 2 n); block 256 (one pixel each)
// part layout: ((chunk*2+n)*512 + oc)*256 + px
// ---------------------------------------------------------------------------
__global__ void __launch_bounds__(256, 2)
conv5_partial(const float* __restrict__ x, const float* __restrict__ w,
              float* __restrict__ part) {
    const int IC = 2048, H = 16, W = 16;
    int chunk = blockIdx.x;
    int oc0   = blockIdx.y * 64;
    int n     = blockIdx.z;
    int tid   = threadIdx.x;
    int y = tid >> 4, xp = tid & 15;

    __shared__ __align__(16) float s_in[8 * 324];   // 8 ic x 18x18 padded
    __shared__ __align__(16) float s_w [8 * 9 * 64];

    float acc[64];
#pragma unroll
    for (int o = 0; o < 64; o++) acc[o] = 0.f;

    const int base_off = y * 18 + xp;
    const int KOFF[9] = {0, 1, 2, 18, 19, 20, 36, 37, 38};

    for (int icb = 0; icb < 32; icb += 8) {
        int ic0 = chunk * 32 + icb;
        // stage padded input 8 x 18 x 18
        for (int i = tid; i < 8 * 324; i += 256) {
            int ic = i / 324, r = i % 324;
            int yy = r / 18 - 1, xx = r % 18 - 1;
            float v = 0.f;
            if ((unsigned)yy < 16u && (unsigned)xx < 16u)
                v = x[(((size_t)n * IC + ic0 + ic) * H + yy) * W + xx];
            s_in[i] = v;
        }
        // stage weights: s_w[(ic*9+t)*64 + oc]
        for (int i = tid; i < 8 * 9 * 64; i += 256) {
            int oc = i & 63;
            int t  = (i >> 6) % 9;
            int ic = i / (64 * 9);
            s_w[i] = w[((size_t)(oc0 + oc) * IC + ic0 + ic) * 9 + t];
        }
        __syncthreads();

#pragma unroll 2
        for (int ic = 0; ic < 8; ic++) {
#pragma unroll
            for (int t = 0; t < 9; t++) {
                float v = s_in[ic * 324 + base_off + KOFF[t]];
                const float4* wp =
                    reinterpret_cast<const float4*>(&s_w[(ic * 9 + t) * 64]);
#pragma unroll
                for (int o = 0; o < 16; o++) {
                    float4 wv = wp[o];
                    acc[4 * o + 0] += v * wv.x;
                    acc[4 * o + 1] += v * wv.y;
                    acc[4 * o + 2] += v * wv.z;
                    acc[4 * o + 3] += v * wv.w;
                }
            }
        }
        __syncthreads();
    }

    size_t base = ((size_t)(chunk * 2 + n) * 512 + oc0) * 256 + tid;
#pragma unroll
    for (int o = 0; o < 64; o++)
        part[base + (size_t)o * 256] = acc[o];
}

// ---------------------------------------------------------------------------
// Generic split-K 1x1 conv -> partial sums.
// grid: (HW/256, ceil(OC/64), 2*split); block 256.  z = chunk*2 + n.
// part layout: ((chunk*2+n)*OC + oc)*HW + px
// Requires C/split % 16 == 0, HW % 256 == 0.
// ---------------------------------------------------------------------------
__global__ void __launch_bounds__(256, 2)
conv1x1_partial(const float* __restrict__ in, const float* __restrict__ w,
                float* __restrict__ part, int C, int OC, int HW, int split) {
    int tid = threadIdx.x;
    int px  = blockIdx.x * 256 + tid;
    int oc0 = blockIdx.y * 64;
    int z   = blockIdx.z;
    int n = z & 1, chunk = z >> 1;
    int Cs = C / split;
    int icbeg = chunk * Cs, icend = icbeg + Cs;

    __shared__ __align__(16) float s_in[16 * 256];
    __shared__ __align__(16) float s_w [16 * 64];

    float acc[64];
#pragma unroll
    for (int o = 0; o < 64; o++) acc[o] = 0.f;

    const float* inb = in + (size_t)n * C * HW;

    for (int ic0 = icbeg; ic0 < icend; ic0 += 16) {
#pragma unroll
        for (int i = 0; i < 16; i++)
            s_in[i * 256 + tid] = inb[(size_t)(ic0 + i) * HW + px];
        for (int i = tid; i < 16 * 64; i += 256) {
            int oc = i & 63, ic = i >> 6;
            s_w[i] = (oc0 + oc < OC) ? w[(size_t)(oc0 + oc) * C + ic0 + ic] : 0.f;
        }
        __syncthreads();

#pragma unroll 4
        for (int ic = 0; ic < 16; ic++) {
            float v = s_in[ic * 256 + tid];
            const float4* wp = reinterpret_cast<const float4*>(&s_w[ic * 64]);
#pragma unroll
            for (int o = 0; o < 16; o++) {
                float4 wv = wp[o];
                acc[4 * o + 0] += v * wv.x;
                acc[4 * o + 1] += v * wv.y;
                acc[4 * o + 2] += v * wv.z;
                acc[4 * o + 3] += v * wv.w;
            }
        }
        __syncthreads();
    }

    int nOC = OC - oc0;
    if (nOC > 64) nOC = 64;
    size_t base = ((size_t)(chunk * 2 + n) * OC + oc0) * HW + px;
#pragma unroll
    for (int o = 0; o < 64; o++)
        if (o < nOC) part[base + (size_t)o * HW] = acc[o];
}

// ---------------------------------------------------------------------------
// Reduce split-K partials + BN (4,OC stacked g,b,m,v) or bias, optional relu.
// idx over 2*OC*HW (n-major).
// ---------------------------------------------------------------------------
__global__ void reduce_kernel(const float* __restrict__ part,
                              const float* __restrict__ bnp,
                              const float* __restrict__ bias,
                              float* __restrict__ out,
                              int split, int OC, int HW, int relu) {
    int idx = blockIdx.x * 256 + threadIdx.x;
    int total = 2 * OC * HW;
    if (idx >= total) return;
    int oc = (idx / HW) % OC;
    size_t slab = (size_t)2 * OC * HW;
    float s = 0.f;
    for (int c = 0; c < split; c++) s += part[(size_t)c * slab + idx];
    if (bnp) {
        float g = bnp[oc], b = bnp[OC + oc], m = bnp[2 * OC + oc],
              v = bnp[3 * OC + oc];
        float sc = g * rsqrtf(v + 1e-5f);
        s = s * sc + (b - m * sc);
    } else if (bias) {
        s += bias[oc];
    }
    if (relu) s = fmaxf(s, 0.f);
    out[idx] = s;
}

// ---------------------------------------------------------------------------
// Bilinear upsample x2, align_corners=True.  (2,C,h,w) -> (2,C,2h,2w)
// ---------------------------------------------------------------------------
__global__ void upsample2(const float* __restrict__ in, float* __restrict__ out,
                          int C, int h, int w) {
    int H = 2 * h, W = 2 * w;
    int idx = blockIdx.x * 256 + threadIdx.x;
    int total = 2 * C * H * W;
    if (idx >= total) return;
    int x  = idx % W;
    int y  = (idx / W) % H;
    int nc = idx / (W * H);

    float ry = (float)(h - 1) / (float)(H - 1);
    float rx = (float)(w - 1) / (float)(W - 1);
    float fy = y * ry, fx = x * rx;
    int y0 = (int)fy; if (y0 > h - 1) y0 = h - 1;
    int x0 = (int)fx; if (x0 > w - 1) x0 = w - 1;
    int y1 = min(y0 + 1, h - 1);
    int x1 = min(x0 + 1, w - 1);
    float wy = fy - (float)y0;
    float wx = fx - (float)x0;

    const float* p = in + (size_t)nc * h * w;
    float a = p[y0 * w + x0] * (1.f - wy) + p[y1 * w + x0] * wy;
    float b = p[y0 * w + x1] * (1.f - wy) + p[y1 * w + x1] * wy;
    out[idx] = a * (1.f - wx) + b * wx;
}

// ---------------------------------------------------------------------------
// Attention: logits[t] = sum_c q[c,y,x]*k[c,y+dy,x+dx] (zero-pad), softmax(9).
// grid: (HW/256, 2); block 256 (one pixel each)
// ---------------------------------------------------------------------------
__global__ void attn_kernel(const float* __restrict__ q,
                            const float* __restrict__ k,
                            float* __restrict__ att, int kd, int H, int W) {
    int tid = threadIdx.x;
    int px  = blockIdx.x * 256 + tid;
    int n   = blockIdx.y;
    int x = px % W, y = px / W;
    size_t HW = (size_t)H * W;

    float a[9];
#pragma unroll
    for (int t = 0; t < 9; t++) a[t] = 0.f;

    const float* qb = q + (size_t)n * kd * HW + px;
    const float* kb = k + (size_t)n * kd * HW;
    for (int c = 0; c < kd; c++) {
        float qv = qb[(size_t)c * HW];
        const float* kc = kb + (size_t)c * HW;
#pragma unroll
        for (int t = 0; t < 9; t++) {
            int dy = (t / 3) * 2 - 2, dx = (t % 3) * 2 - 2;
            int yy = y + dy, xx = x + dx;
            if ((unsigned)yy < (unsigned)H && (unsigned)xx < (unsigned)W)
                a[t] += qv * kc[yy * W + xx];
        }
    }
    float mx = a[0];
#pragma unroll
    for (int t = 1; t < 9; t++) mx = fmaxf(mx, a[t]);
    float s = 0.f;
#pragma unroll
    for (int t = 0; t < 9; t++) { a[t] = __expf(a[t] - mx); s += a[t]; }
    float inv = 1.f / s;
#pragma unroll
    for (int t = 0; t < 9; t++)
        att[((size_t)n * 9 + t) * HW + px] = a[t] * inv;
}

// ---------------------------------------------------------------------------
// Aggregation: out[c,y,x] = sum_t att[t,y,x] * up[c,y+dy,x+dx] (zero-pad).
// grid: (HW/256, C/8, 2); block 256; att tile cached in smem.
// ---------------------------------------------------------------------------
__global__ void agg_kernel(const float* __restrict__ att,
                           const float* __restrict__ up,
                           float* __restrict__ out, int C, int H, int W) {
    int tid = threadIdx.x;
    int px  = blockIdx.x * 256 + tid;
    int c0  = blockIdx.y * 8;
    int n   = blockIdx.z;
    size_t HW = (size_t)H * W;

    __shared__ float s_att[9][256];
#pragma unroll
    for (int t = 0; t < 9; t++)
        s_att[t][tid] = att[((size_t)n * 9 + t) * HW + px];
    __syncthreads();

    int x = px % W, y = px / W;
    const float* upb = up + ((size_t)n * C + c0) * HW;
    float* ob        = out + ((size_t)n * C + c0) * HW;

    for (int c = 0; c < 8; c++) {
        const float* uc = upb + (size_t)c * HW;
        float s = 0.f;
#pragma unroll
        for (int t = 0; t < 9; t++) {
            int dy = (t / 3) * 2 - 2, dx = (t % 3) * 2 - 2;
            int yy = y + dy, xx = x + dx;
            if ((unsigned)yy < (unsigned)H && (unsigned)xx < (unsigned)W)
                s += s_att[t][tid] * uc[yy * W + xx];
        }
        ob[(size_t)c * HW + px] = s;
    }
}

// ---------------------------------------------------------------------------
// Orchestration
// ---------------------------------------------------------------------------
extern "C" void kernel_launch(void* const* d_in, const int* in_sizes, int n_in,
                              void* d_out, int out_size) {
    (void)in_sizes; (void)n_in; (void)out_size;
    const float* c1      = (const float*)d_in[0];
    const float* c2      = (const float*)d_in[1];
    const float* c3      = (const float*)d_in[2];
    const float* c4      = (const float*)d_in[3];
    // c20 (d_in[4]) unused by the math path (only c2/c30/c40 feed k projections)
    const float* c30     = (const float*)d_in[5];
    const float* c40     = (const float*)d_in[6];
    const float* conv5_w = (const float*)d_in[7];
    const float* bn5     = (const float*)d_in[8];
    const float* conv6_w = (const float*)d_in[9];
    const float* conv6_b = (const float*)d_in[10];
    const float* lu4_w1  = (const float*)d_in[11];
    const float* lu4_bn1 = (const float*)d_in[12];
    const float* lu4_w2  = (const float*)d_in[13];
    const float* lu4_bn2 = (const float*)d_in[14];
    const float* lu3_w1  = (const float*)d_in[15];
    const float* lu3_bn1 = (const float*)d_in[16];
    const float* lu3_w2  = (const float*)d_in[17];
    const float* lu3_bn2 = (const float*)d_in[18];
    const float* lu2_w1  = (const float*)d_in[19];
    const float* lu2_bn1 = (const float*)d_in[20];
    const float* lu2_w2  = (const float*)d_in[21];
    const float* lu2_bn2 = (const float*)d_in[22];

    float *part, *outA, *outB, *up, *q, *k, *klo, *att;
    cudaGetSymbolAddress((void**)&part, g_part);
    cudaGetSymbolAddress((void**)&outA, g_outA);
    cudaGetSymbolAddress((void**)&outB, g_outB);
    cudaGetSymbolAddress((void**)&up,   g_up);
    cudaGetSymbolAddress((void**)&q,    g_q);
    cudaGetSymbolAddress((void**)&k,    g_k);
    cudaGetSymbolAddress((void**)&klo,  g_klo);
    cudaGetSymbolAddress((void**)&att,  g_att);

    // ---- conv5 + BN + ReLU -> outA (2,512,16,16) ----
    conv5_partial<<<dim3(64, 8, 2), 256>>>(c4, conv5_w, part);
    reduce_kernel<<<(2 * 512 * 256) / 256, 256>>>(part, bn5, nullptr, outA,
                                                  64, 512, 256, 1);

    // ---- localUp4: H=W=32, kd=128 ----
    conv1x1_partial<<<dim3(4, 2, 16), 256>>>(c3, lu4_w1, part, 1024, 128, 1024, 8);
    reduce_kernel<<<(2 * 128 * 1024) / 256, 256>>>(part, lu4_bn1, nullptr, q,
                                                   8, 128, 1024, 0);
    conv1x1_partial<<<dim3(1, 2, 32), 256>>>(c40, lu4_w2, part, 2048, 128, 256, 16);
    reduce_kernel<<<(2 * 128 * 256) / 256, 256>>>(part, lu4_bn2, nullptr, klo,
                                                  16, 128, 256, 0);
    upsample2<<<(2 * 128 * 1024) / 256, 256>>>(klo, k, 128, 16, 16);
    upsample2<<<(2 * 512 * 1024) / 256, 256>>>(outA, up, 512, 16, 16);
    attn_kernel<<<dim3(4, 2), 256>>>(q, k, att, 128, 32, 32);
    agg_kernel<<<dim3(4, 64, 2), 256>>>(att, up, outB, 512, 32, 32);

    // ---- localUp3: H=W=64, kd=64 ----
    conv1x1_partial<<<dim3(16, 1, 8), 256>>>(c2, lu3_w1, part, 512, 64, 4096, 4);
    reduce_kernel<<<(2 * 64 * 4096) / 256, 256>>>(part, lu3_bn1, nullptr, q,
                                                  4, 64, 4096, 0);
    conv1x1_partial<<<dim3(4, 1, 16), 256>>>(c30, lu3_w2, part, 1024, 64, 1024, 8);
    reduce_kernel<<<(2 * 64 * 1024) / 256, 256>>>(part, lu3_bn2, nullptr, klo,
                                                  8, 64, 1024, 0);
    upsample2<<<(2 * 64 * 4096) / 256, 256>>>(klo, k, 64, 32, 32);
    upsample2<<<(2 * 512 * 4096) / 256, 256>>>(outB, up, 512, 32, 32);
    attn_kernel<<<dim3(16, 2), 256>>>(q, k, att, 64, 64, 64);
    agg_kernel<<<dim3(16, 64, 2), 256>>>(att, up, outA, 512, 64, 64);

    // ---- localUp2: H=W=128, kd=64 ----
    conv1x1_partial<<<dim3(64, 1, 4), 256>>>(c1, lu2_w1, part, 256, 64, 16384, 2);
    reduce_kernel<<<(2 * 64 * 16384) / 256, 256>>>(part, lu2_bn1, nullptr, q,
                                                   2, 64, 16384, 0);
    conv1x1_partial<<<dim3(16, 1, 8), 256>>>(c2, lu2_w2, part, 512, 64, 4096, 4);
    reduce_kernel<<<(2 * 64 * 4096) / 256, 256>>>(part, lu2_bn2, nullptr, klo,
                                                  4, 64, 4096, 0);
    upsample2<<<(2 * 64 * 16384) / 256, 256>>>(klo, k, 64, 64, 64);
    upsample2<<<(2 * 512 * 16384) / 256, 256>>>(outA, up, 512, 64, 64);
    attn_kernel<<<dim3(64, 2), 256>>>(q, k, att, 64, 128, 128);
    agg_kernel<<<dim3(64, 64, 2), 256>>>(att, up, outB, 512, 128, 128);

    // ---- conv6 (1x1, 512->19) + bias -> d_out (2,19,128,128) ----
    conv1x1_partial<<<dim3(64, 1, 4), 256>>>(outB, conv6_w, part, 512, 19, 16384, 2);
    reduce_kernel<<<(2 * 19 * 16384 + 255) / 256, 256>>>(part, nullptr, conv6_b,
                                                         (float*)d_out,
                                                         2, 19, 16384, 0);
}

// round 7
// speedup vs baseline: 1.5023x; 1.5023x over previous
#include <cuda_runtime.h>
#include <cuda_bf16.h>
#include <cstdint>

// ---------------------------------------------------------------------------
// Scratch (device globals -- no allocation allowed)
// ---------------------------------------------------------------------------
__device__ float g_part[16777216];   // split-K partials (max: conv5 64*2*512*256)
__device__ float g_outA[16777216];   // ping  (2*512*128*128 max)
__device__ float g_outB[16777216];   // pong
__device__ float g_up  [16777216];   // upsampled out_prev
__device__ float g_q   [2097152];    // q maps (max 2*64*128*128)
__device__ float g_k   [2097152];    // hi-res k maps
__device__ float g_klo [524288];     // low-res k maps
__device__ float g_att [294912];     // attention 2*9*128*128 max
__device__ float g_wrep[10000000];   // repacked weights (conv5 9.44M + 1x1s)

// repacked-weight offsets inside g_wrep
#define W5_OFF    0                        // 2048*9*512 = 9437184
#define W_LU4A    9437184                  // 1024*128
#define W_LU4B    (W_LU4A + 131072)        // 2048*128
#define W_LU3A    (W_LU4B + 262144)        // 512*64
#define W_LU3B    (W_LU3A + 32768)         // 1024*64
#define W_LU2A    (W_LU3B + 65536)         // 256*64
#define W_LU2B    (W_LU2A + 16384)         // 512*64
#define W_C6      (W_LU2B + 32768)         // 512*19

// ---------------------------------------------------------------------------
// Packed fp32x2 helpers (Blackwell paired-FP32 pipe)
// ---------------------------------------------------------------------------
__device__ __forceinline__ void fma2(unsigned long long& d,
                                     unsigned long long a,
                                     unsigned long long b) {
    asm("fma.rn.f32x2 %0, %1, %2, %0;" : "+l"(d) : "l"(a), "l"(b));
}
__device__ __forceinline__ unsigned long long bcast2(float v) {
    unsigned long long r;
    unsigned u = __float_as_uint(v);
    asm("mov.b64 %0, {%1, %1};" : "=l"(r) : "r"(u));
    return r;
}
__device__ __forceinline__ float2 unpack2(unsigned long long p) {
    unsigned lo, hi;
    asm("mov.b64 {%0, %1}, %2;" : "=r"(lo), "=r"(hi) : "l"(p));
    return make_float2(__uint_as_float(lo), __uint_as_float(hi));
}

// ---------------------------------------------------------------------------
// Weight repacks (coalesced staging layouts)
// conv5: OIHW (512,2048,3,3) -> [ic][tap][oc]  (oc contiguous)
// 1x1:   (OC,C)              -> [ic][oc]       (oc contiguous)
// ---------------------------------------------------------------------------
__global__ void repack_w5(const float* __restrict__ w, float* __restrict__ wt) {
    int idx = blockIdx.x * 256 + threadIdx.x;
    if (idx >= 2048 * 9 * 512) return;
    int oc = idx & 511;
    int t  = (idx >> 9) % 9;
    int ic = idx / (512 * 9);
    wt[idx] = w[((size_t)oc * 2048 + ic) * 9 + t];
}
__global__ void repack_w1x1(const float* __restrict__ w, float* __restrict__ wt,
                            int OC, int C) {
    int idx = blockIdx.x * 256 + threadIdx.x;
    if (idx >= OC * C) return;
    int oc = idx % OC, ic = idx / OC;
    wt[idx] = w[(size_t)oc * C + ic];
}

// ---------------------------------------------------------------------------
// conv5: 3x3 conv, IC=2048 -> OC=512, 16x16, pad 1.  Split-K partial sums.
// grid: (64 ic-chunks of 32, 8 oc-tiles of 64, 2 n); block 256 (one pixel each)
// part layout: ((chunk*2+n)*512 + oc)*256 + px
// weights pre-repacked: wt[((ic*9)+t)*512 + oc]
// ---------------------------------------------------------------------------
__global__ void __launch_bounds__(256, 2)
conv5_partial(const float* __restrict__ x, const float* __restrict__ wt,
              float* __restrict__ part) {
    const int IC = 2048, H = 16, W = 16;
    int chunk = blockIdx.x;
    int oc0   = blockIdx.y * 64;
    int n     = blockIdx.z;
    int tid   = threadIdx.x;
    int y = tid >> 4, xp = tid & 15;

    __shared__ __align__(16) float s_in[8 * 324];   // 8 ic x 18x18 padded
    __shared__ __align__(16) float s_w [8 * 9 * 64];

    unsigned long long acc[32];                      // 32 oc-pairs
#pragma unroll
    for (int o = 0; o < 32; o++) acc[o] = 0ull;

    const int base_off = y * 18 + xp;
    const int KOFF[9] = {0, 1, 2, 18, 19, 20, 36, 37, 38};

    for (int icb = 0; icb < 32; icb += 8) {
        int ic0 = chunk * 32 + icb;
        // stage padded input 8 ic x 18 x 18
        for (int i = tid; i < 8 * 324; i += 256) {
            int ic = i / 324, r = i % 324;
            int yy = r / 18 - 1, xx = r % 18 - 1;
            float v = 0.f;
            if ((unsigned)yy < 16u && (unsigned)xx < 16u)
                v = x[(((size_t)n * IC + ic0 + ic) * H + yy) * W + xx];
            s_in[i] = v;
        }
        // stage weights (coalesced 64-float runs): s_w[(ic*9+t)*64 + oc]
        for (int i = tid; i < 8 * 9 * 64; i += 256) {
            int oc = i & 63;
            int t  = (i >> 6) % 9;
            int ic = i / (64 * 9);
            s_w[i] = wt[((size_t)(ic0 + ic) * 9 + t) * 512 + oc0 + oc];
        }
        __syncthreads();

#pragma unroll 2
        for (int ic = 0; ic < 8; ic++) {
#pragma unroll
            for (int t = 0; t < 9; t++) {
                unsigned long long vv =
                    bcast2(s_in[ic * 324 + base_off + KOFF[t]]);
                const ulonglong2* wp =
                    reinterpret_cast<const ulonglong2*>(&s_w[(ic * 9 + t) * 64]);
#pragma unroll
                for (int o = 0; o < 16; o++) {
                    ulonglong2 wv = wp[o];
                    fma2(acc[2 * o + 0], vv, wv.x);
                    fma2(acc[2 * o + 1], vv, wv.y);
                }
            }
        }
        __syncthreads();
    }

    size_t base = ((size_t)(chunk * 2 + n) * 512 + oc0) * 256 + tid;
#pragma unroll
    for (int p = 0; p < 32; p++) {
        float2 f = unpack2(acc[p]);
        part[base + (size_t)(2 * p + 0) * 256] = f.x;
        part[base + (size_t)(2 * p + 1) * 256] = f.y;
    }
}

// ---------------------------------------------------------------------------
// Generic split-K 1x1 conv -> partial sums (weights pre-transposed [C][OC]).
// grid: (HW/256, ceil(OC/64), 2*split); block 256.  z = chunk*2 + n.
// part layout: ((chunk*2+n)*OC + oc)*HW + px
// Requires C/split % 16 == 0, HW % 256 == 0.
// ---------------------------------------------------------------------------
__global__ void __launch_bounds__(256, 2)
conv1x1_partial(const float* __restrict__ in, const float* __restrict__ wt,
                float* __restrict__ part, int C, int OC, int HW, int split) {
    int tid = threadIdx.x;
    int px  = blockIdx.x * 256 + tid;
    int oc0 = blockIdx.y * 64;
    int z   = blockIdx.z;
    int n = z & 1, chunk = z >> 1;
    int Cs = C / split;
    int icbeg = chunk * Cs, icend = icbeg + Cs;

    __shared__ __align__(16) float s_in[16 * 256];
    __shared__ __align__(16) float s_w [16 * 64];

    unsigned long long acc[32];
#pragma unroll
    for (int o = 0; o < 32; o++) acc[o] = 0ull;

    const float* inb = in + (size_t)n * C * HW;

    for (int ic0 = icbeg; ic0 < icend; ic0 += 16) {
#pragma unroll
        for (int i = 0; i < 16; i++)
            s_in[i * 256 + tid] = inb[(size_t)(ic0 + i) * HW + px];
        for (int i = tid; i < 16 * 64; i += 256) {
            int oc = i & 63, ic = i >> 6;
            s_w[i] = (oc0 + oc < OC) ? wt[(size_t)(ic0 + ic) * OC + oc0 + oc]
                                     : 0.f;
        }
        __syncthreads();

#pragma unroll 4
        for (int ic = 0; ic < 16; ic++) {
            unsigned long long vv = bcast2(s_in[ic * 256 + tid]);
            const ulonglong2* wp =
                reinterpret_cast<const ulonglong2*>(&s_w[ic * 64]);
#pragma unroll
            for (int o = 0; o < 16; o++) {
                ulonglong2 wv = wp[o];
                fma2(acc[2 * o + 0], vv, wv.x);
                fma2(acc[2 * o + 1], vv, wv.y);
            }
        }
        __syncthreads();
    }

    int nOC = OC - oc0;
    if (nOC > 64) nOC = 64;
    size_t base = ((size_t)(chunk * 2 + n) * OC + oc0) * HW + px;
#pragma unroll
    for (int p = 0; p < 32; p++) {
        float2 f = unpack2(acc[p]);
        if (2 * p + 0 < nOC) part[base + (size_t)(2 * p + 0) * HW] = f.x;
        if (2 * p + 1 < nOC) part[base + (size_t)(2 * p + 1) * HW] = f.y;
    }
}

// ---------------------------------------------------------------------------
// Reduce split-K partials + BN (4,OC stacked g,b,m,v) or bias, optional relu.
// ---------------------------------------------------------------------------
__global__ void reduce_kernel(const float* __restrict__ part,
                              const float* __restrict__ bnp,
                              const float* __restrict__ bias,
                              float* __restrict__ out,
                              int split, int OC, int HW, int relu) {
    int idx = blockIdx.x * 256 + threadIdx.x;
    int total = 2 * OC * HW;
    if (idx >= total) return;
    int oc = (idx / HW) % OC;
    size_t slab = (size_t)2 * OC * HW;
    float s = 0.f;
    for (int c = 0; c < split; c++) s += part[(size_t)c * slab + idx];
    if (bnp) {
        float g = bnp[oc], b = bnp[OC + oc], m = bnp[2 * OC + oc],
              v = bnp[3 * OC + oc];
        float sc = g * rsqrtf(v + 1e-5f);
        s = s * sc + (b - m * sc);
    } else if (bias) {
        s += bias[oc];
    }
    if (relu) s = fmaxf(s, 0.f);
    out[idx] = s;
}

// ---------------------------------------------------------------------------
// Bilinear upsample x2, align_corners=True.  (2,C,h,w) -> (2,C,2h,2w)
// ---------------------------------------------------------------------------
__global__ void upsample2(const float* __restrict__ in, float* __restrict__ out,
                          int C, int h, int w) {
    int H = 2 * h, W = 2 * w;
    int idx = blockIdx.x * 256 + threadIdx.x;
    int total = 2 * C * H * W;
    if (idx >= total) return;
    int x  = idx % W;
    int y  = (idx / W) % H;
    int nc = idx / (W * H);

    float ry = (float)(h - 1) / (float)(H - 1);
    float rx = (float)(w - 1) / (float)(W - 1);
    float fy = y * ry, fx = x * rx;
    int y0 = (int)fy; if (y0 > h - 1) y0 = h - 1;
    int x0 = (int)fx; if (x0 > w - 1) x0 = w - 1;
    int y1 = min(y0 + 1, h - 1);
    int x1 = min(x0 + 1, w - 1);
    float wy = fy - (float)y0;
    float wx = fx - (float)x0;

    const float* p = in + (size_t)nc * h * w;
    float a = p[y0 * w + x0] * (1.f - wy) + p[y1 * w + x0] * wy;
    float b = p[y0 * w + x1] * (1.f - wy) + p[y1 * w + x1] * wy;
    out[idx] = a * (1.f - wx) + b * wx;
}

// ---------------------------------------------------------------------------
// Attention: logits[t] = sum_c q[c,y,x]*k[c,y+dy,x+dx] (zero-pad), softmax(9).
// grid: (HW/256, 2); block 256 (one pixel each)
// ---------------------------------------------------------------------------
__global__ void attn_kernel(const float* __restrict__ q,
                            const float* __restrict__ k,
                            float* __restrict__ att, int kd, int H, int W) {
    int tid = threadIdx.x;
    int px  = blockIdx.x * 256 + tid;
    int n   = blockIdx.y;
    int x = px % W, y = px / W;
    size_t HW = (size_t)H * W;

    float a[9];
#pragma unroll
    for (int t = 0; t < 9; t++) a[t] = 0.f;

    const float* qb = q + (size_t)n * kd * HW + px;
    const float* kb = k + (size_t)n * kd * HW;
    for (int c = 0; c < kd; c++) {
        float qv = qb[(size_t)c * HW];
        const float* kc = kb + (size_t)c * HW;
#pragma unroll
        for (int t = 0; t < 9; t++) {
            int dy = (t / 3) * 2 - 2, dx = (t % 3) * 2 - 2;
            int yy = y + dy, xx = x + dx;
            if ((unsigned)yy < (unsigned)H && (unsigned)xx < (unsigned)W)
                a[t] += qv * kc[yy * W + xx];
        }
    }
    float mx = a[0];
#pragma unroll
    for (int t = 1; t < 9; t++) mx = fmaxf(mx, a[t]);
    float s = 0.f;
#pragma unroll
    for (int t = 0; t < 9; t++) { a[t] = __expf(a[t] - mx); s += a[t]; }
    float inv = 1.f / s;
#pragma unroll
    for (int t = 0; t < 9; t++)
        att[((size_t)n * 9 + t) * HW + px] = a[t] * inv;
}

// ---------------------------------------------------------------------------
// Aggregation: out[c,y,x] = sum_t att[t,y,x] * up[c,y+dy,x+dx] (zero-pad).
// grid: (HW/256, C/8, 2); block 256; att tile cached in smem.
// ---------------------------------------------------------------------------
__global__ void agg_kernel(const float* __restrict__ att,
                           const float* __restrict__ up,
                           float* __restrict__ out, int C, int H, int W) {
    int tid = threadIdx.x;
    int px  = blockIdx.x * 256 + tid;
    int c0  = blockIdx.y * 8;
    int n   = blockIdx.z;
    size_t HW = (size_t)H * W;

    __shared__ float s_att[9][256];
#pragma unroll
    for (int t = 0; t < 9; t++)
        s_att[t][tid] = att[((size_t)n * 9 + t) * HW + px];
    __syncthreads();

    int x = px % W, y = px / W;
    const float* upb = up + ((size_t)n * C + c0) * HW;
    float* ob        = out + ((size_t)n * C + c0) * HW;

    for (int c = 0; c < 8; c++) {
        const float* uc = upb + (size_t)c * HW;
        float s = 0.f;
#pragma unroll
        for (int t = 0; t < 9; t++) {
            int dy = (t / 3) * 2 - 2, dx = (t % 3) * 2 - 2;
            int yy = y + dy, xx = x + dx;
            if ((unsigned)yy < (unsigned)H && (unsigned)xx < (unsigned)W)
                s += s_att[t][tid] * uc[yy * W + xx];
        }
        ob[(size_t)c * HW + px] = s;
    }
}

// ---------------------------------------------------------------------------
// Orchestration
// ---------------------------------------------------------------------------
extern "C" void kernel_launch(void* const* d_in, const int* in_sizes, int n_in,
                              void* d_out, int out_size) {
    (void)in_sizes; (void)n_in; (void)out_size;
    const float* c1      = (const float*)d_in[0];
    const float* c2      = (const float*)d_in[1];
    const float* c3      = (const float*)d_in[2];
    const float* c4      = (const float*)d_in[3];
    // c20 (d_in[4]) unused by the math path
    const float* c30     = (const float*)d_in[5];
    const float* c40     = (const float*)d_in[6];
    const float* conv5_w = (const float*)d_in[7];
    const float* bn5     = (const float*)d_in[8];
    const float* conv6_w = (const float*)d_in[9];
    const float* conv6_b = (const float*)d_in[10];
    const float* lu4_w1  = (const float*)d_in[11];
    const float* lu4_bn1 = (const float*)d_in[12];
    const float* lu4_w2  = (const float*)d_in[13];
    const float* lu4_bn2 = (const float*)d_in[14];
    const float* lu3_w1  = (const float*)d_in[15];
    const float* lu3_bn1 = (const float*)d_in[16];
    const float* lu3_w2  = (const float*)d_in[17];
    const float* lu3_bn2 = (const float*)d_in[18];
    const float* lu2_w1  = (const float*)d_in[19];
    const float* lu2_bn1 = (const float*)d_in[20];
    const float* lu2_w2  = (const float*)d_in[21];
    const float* lu2_bn2 = (const float*)d_in[22];

    float *part, *outA, *outB, *up, *q, *k, *klo, *att, *wrep;
    cudaGetSymbolAddress((void**)&part, g_part);
    cudaGetSymbolAddress((void**)&outA, g_outA);
    cudaGetSymbolAddress((void**)&outB, g_outB);
    cudaGetSymbolAddress((void**)&up,   g_up);
    cudaGetSymbolAddress((void**)&q,    g_q);
    cudaGetSymbolAddress((void**)&k,    g_k);
    cudaGetSymbolAddress((void**)&klo,  g_klo);
    cudaGetSymbolAddress((void**)&att,  g_att);
    cudaGetSymbolAddress((void**)&wrep, g_wrep);

    // ---- weight repacks (coalesced staging layouts) ----
    repack_w5  <<<(2048 * 9 * 512 + 255) / 256, 256>>>(conv5_w, wrep + W5_OFF);
    repack_w1x1<<<(128 * 1024 + 255) / 256, 256>>>(lu4_w1,  wrep + W_LU4A, 128, 1024);
    repack_w1x1<<<(128 * 2048 + 255) / 256, 256>>>(lu4_w2,  wrep + W_LU4B, 128, 2048);
    repack_w1x1<<<(64 * 512   + 255) / 256, 256>>>(lu3_w1,  wrep + W_LU3A, 64, 512);
    repack_w1x1<<<(64 * 1024  + 255) / 256, 256>>>(lu3_w2,  wrep + W_LU3B, 64, 1024);
    repack_w1x1<<<(64 * 256   + 255) / 256, 256>>>(lu2_w1,  wrep + W_LU2A, 64, 256);
    repack_w1x1<<<(64 * 512   + 255) / 256, 256>>>(lu2_w2,  wrep + W_LU2B, 64, 512);
    repack_w1x1<<<(19 * 512   + 255) / 256, 256>>>(conv6_w, wrep + W_C6,   19, 512);

    // ---- conv5 + BN + ReLU -> outA (2,512,16,16) ----
    conv5_partial<<<dim3(64, 8, 2), 256>>>(c4, wrep + W5_OFF, part);
    reduce_kernel<<<(2 * 512 * 256) / 256, 256>>>(part, bn5, nullptr, outA,
                                                  64, 512, 256, 1);

    // ---- localUp4: H=W=32, kd=128 ----
    conv1x1_partial<<<dim3(4, 2, 16), 256>>>(c3, wrep + W_LU4A, part, 1024, 128, 1024, 8);
    reduce_kernel<<<(2 * 128 * 1024) / 256, 256>>>(part, lu4_bn1, nullptr, q,
                                                   8, 128, 1024, 0);
    conv1x1_partial<<<dim3(1, 2, 32), 256>>>(c40, wrep + W_LU4B, part, 2048, 128, 256, 16);
    reduce_kernel<<<(2 * 128 * 256) / 256, 256>>>(part, lu4_bn2, nullptr, klo,
                                                  16, 128, 256, 0);
    upsample2<<<(2 * 128 * 1024) / 256, 256>>>(klo, k, 128, 16, 16);
    upsample2<<<(2 * 512 * 1024) / 256, 256>>>(outA, up, 512, 16, 16);
    attn_kernel<<<dim3(4, 2), 256>>>(q, k, att, 128, 32, 32);
    agg_kernel<<<dim3(4, 64, 2), 256>>>(att, up, outB, 512, 32, 32);

    // ---- localUp3: H=W=64, kd=64 ----
    conv1x1_partial<<<dim3(16, 1, 8), 256>>>(c2, wrep + W_LU3A, part, 512, 64, 4096, 4);
    reduce_kernel<<<(2 * 64 * 4096) / 256, 256>>>(part, lu3_bn1, nullptr, q,
                                                  4, 64, 4096, 0);
    conv1x1_partial<<<dim3(4, 1, 16), 256>>>(c30, wrep + W_LU3B, part, 1024, 64, 1024, 8);
    reduce_kernel<<<(2 * 64 * 1024) / 256, 256>>>(part, lu3_bn2, nullptr, klo,
                                                  8, 64, 1024, 0);
    upsample2<<<(2 * 64 * 4096) / 256, 256>>>(klo, k, 64, 32, 32);
    upsample2<<<(2 * 512 * 4096) / 256, 256>>>(outB, up, 512, 32, 32);
    attn_kernel<<<dim3(16, 2), 256>>>(q, k, att, 64, 64, 64);
    agg_kernel<<<dim3(16, 64, 2), 256>>>(att, up, outA, 512, 64, 64);

    // ---- localUp2: H=W=128, kd=64 ----
    conv1x1_partial<<<dim3(64, 1, 4), 256>>>(c1, wrep + W_LU2A, part, 256, 64, 16384, 2);
    reduce_kernel<<<(2 * 64 * 16384) / 256, 256>>>(part, lu2_bn1, nullptr, q,
                                                   2, 64, 16384, 0);
    conv1x1_partial<<<dim3(16, 1, 8), 256>>>(c2, wrep + W_LU2B, part, 512, 64, 4096, 4);
    reduce_kernel<<<(2 * 64 * 4096) / 256, 256>>>(part, lu2_bn2, nullptr, klo,
                                                  4, 64, 4096, 0);
    upsample2<<<(2 * 64 * 16384) / 256, 256>>>(klo, k, 64, 64, 64);
    upsample2<<<(2 * 512 * 16384) / 256, 256>>>(outA, up, 512, 64, 64);
    attn_kernel<<<dim3(64, 2), 256>>>(q, k, att, 64, 128, 128);
    agg_kernel<<<dim3(64, 64, 2), 256>>>(att, up, outB, 512, 128, 128);

    // ---- conv6 (1x1, 512->19) + bias -> d_out (2,19,128,128) ----
    conv1x1_partial<<<dim3(64, 1, 4), 256>>>(outB, wrep + W_C6, part, 512, 19, 16384, 2);
    reduce_kernel<<<(2 * 19 * 16384 + 255) / 256, 256>>>(part, nullptr, conv6_b,
                                                         (float*)d_out,
                                                         2, 19, 16384, 0);
}

// round 9
// speedup vs baseline: 1.5548x; 1.0350x over previous
#include <cuda_runtime.h>
#include <cuda_bf16.h>
#include <cstdint>

// ---------------------------------------------------------------------------
// Scratch (device globals -- no allocation allowed)
// ---------------------------------------------------------------------------
__device__ float g_part[16777216];   // split-K partials
__device__ float g_outA[16777216];   // ping  (2*512*128*128 max)
__device__ float g_outB[16777216];   // pong
__device__ float g_up  [16777216];   // upsampled out_prev
__device__ float g_q   [2097152];    // q maps (max 2*64*128*128)
__device__ float g_k   [2097152];    // hi-res k maps
__device__ float g_klo [524288];     // low-res k maps
__device__ float g_att [294912];     // attention 2*9*128*128 max
__device__ float g_wrep[10000000];   // repacked weights (conv5 9.44M + 1x1s)

// repacked-weight offsets inside g_wrep
#define W5_OFF    0                        // 2048*9*512 = 9437184
#define W_LU4A    9437184                  // 1024*128
#define W_LU4B    (W_LU4A + 131072)        // 2048*128
#define W_LU3A    (W_LU4B + 262144)        // 512*64
#define W_LU3B    (W_LU3A + 32768)         // 1024*64
#define W_LU2A    (W_LU3B + 65536)         // 256*64
#define W_LU2B    (W_LU2A + 16384)         // 512*64
#define W_C6      (W_LU2B + 32768)         // 512*19

// ---------------------------------------------------------------------------
// Packed fp32x2 helpers (Blackwell paired-FP32 pipe)
// ---------------------------------------------------------------------------
__device__ __forceinline__ void fma2(unsigned long long& d,
                                     unsigned long long a,
                                     unsigned long long b) {
    asm("fma.rn.f32x2 %0, %1, %2, %0;" : "+l"(d) : "l"(a), "l"(b));
}
__device__ __forceinline__ unsigned long long bcast2(float v) {
    unsigned long long r;
    unsigned u = __float_as_uint(v);
    asm("mov.b64 %0, {%1, %1};" : "=l"(r) : "r"(u));
    return r;
}
__device__ __forceinline__ float2 unpack2(unsigned long long p) {
    unsigned lo, hi;
    asm("mov.b64 {%0, %1}, %2;" : "=r"(lo), "=r"(hi) : "l"(p));
    return make_float2(__uint_as_float(lo), __uint_as_float(hi));
}

// ---------------------------------------------------------------------------
// Generic tiled transpose: w (R x C, row-major) -> wt (C x R).
// Both global access patterns fully coalesced (32x32 smem tile, padded).
// conv5 weights (512, 2048*9) -> (ic*9, oc); 1x1 (OC, C) -> (C, OC).
// grid: (ceil(C/32), ceil(R/32)); block 256.
// ---------------------------------------------------------------------------
__global__ void transpose_w(const float* __restrict__ w, float* __restrict__ wt,
                            int R, int C) {
    __shared__ float tile[32][33];
    int c0 = blockIdx.x * 32;
    int r0 = blockIdx.y * 32;
    int tx = threadIdx.x & 31, ty = threadIdx.x >> 5;   // ty in 0..7
#pragma unroll
    for (int i = ty; i < 32; i += 8) {
        int r = r0 + i, c = c0 + tx;
        tile[i][tx] = (r < R && c < C) ? w[(size_t)r * C + c] : 0.f;
    }
    __syncthreads();
#pragma unroll
    for (int i = ty; i < 32; i += 8) {
        int c = c0 + i, r = r0 + tx;
        if (c < C && r < R) wt[(size_t)c * R + r] = tile[tx][i];
    }
}

// ---------------------------------------------------------------------------
// conv5: 3x3 conv, IC=2048 -> OC=512, 16x16, pad 1.  Split-K partial sums.
// grid: (32 ic-chunks of 64, 8 oc-tiles of 64, 2 n); block 256 (one pixel each)
// part layout: ((chunk*2+n)*512 + oc)*256 + px
// weights pre-repacked: wt[((ic*9)+t)*512 + oc]
// ---------------------------------------------------------------------------
__global__ void __launch_bounds__(256, 2)
conv5_partial(const float* __restrict__ x, const float* __restrict__ wt,
              float* __restrict__ part) {
    const int IC = 2048, H = 16, W = 16;
    int chunk = blockIdx.x;
    int oc0   = blockIdx.y * 64;
    int n     = blockIdx.z;
    int tid   = threadIdx.x;
    int y = tid >> 4, xp = tid & 15;

    __shared__ __align__(16) float s_in[8 * 324];   // 8 ic x 18x18 padded
    __shared__ __align__(16) float s_w [8 * 9 * 64];

    unsigned long long acc[32];                      // 32 oc-pairs
#pragma unroll
    for (int o = 0; o < 32; o++) acc[o] = 0ull;

    const int base_off = y * 18 + xp;
    const int KOFF[9] = {0, 1, 2, 18, 19, 20, 36, 37, 38};

    for (int icb = 0; icb < 64; icb += 8) {
        int ic0 = chunk * 64 + icb;
        // stage padded input 8 ic x 18 x 18
        for (int i = tid; i < 8 * 324; i += 256) {
            int ic = i / 324, r = i % 324;
            int yy = r / 18 - 1, xx = r % 18 - 1;
            float v = 0.f;
            if ((unsigned)yy < 16u && (unsigned)xx < 16u)
                v = x[(((size_t)n * IC + ic0 + ic) * H + yy) * W + xx];
            s_in[i] = v;
        }
        // stage weights (coalesced 64-float runs): s_w[(ic*9+t)*64 + oc]
        for (int i = tid; i < 8 * 9 * 64; i += 256) {
            int oc = i & 63;
            int t  = (i >> 6) % 9;
            int ic = i / (64 * 9);
            s_w[i] = wt[((size_t)(ic0 + ic) * 9 + t) * 512 + oc0 + oc];
        }
        __syncthreads();

#pragma unroll 2
        for (int ic = 0; ic < 8; ic++) {
#pragma unroll
            for (int t = 0; t < 9; t++) {
                unsigned long long vv =
                    bcast2(s_in[ic * 324 + base_off + KOFF[t]]);
                const ulonglong2* wp =
                    reinterpret_cast<const ulonglong2*>(&s_w[(ic * 9 + t) * 64]);
#pragma unroll
                for (int o = 0; o < 16; o++) {
                    ulonglong2 wv = wp[o];
                    fma2(acc[2 * o + 0], vv, wv.x);
                    fma2(acc[2 * o + 1], vv, wv.y);
                }
            }
        }
        __syncthreads();
    }

    size_t base = ((size_t)(chunk * 2 + n) * 512 + oc0) * 256 + tid;
#pragma unroll
    for (int p = 0; p < 32; p++) {
        float2 f = unpack2(acc[p]);
        part[base + (size_t)(2 * p + 0) * 256] = f.x;
        part[base + (size_t)(2 * p + 1) * 256] = f.y;
    }
}

// ---------------------------------------------------------------------------
// Generic split-K 1x1 conv -> partial sums (weights pre-transposed [C][OC]).
// grid: (HW/256, ceil(OC/64), 2*split); block 256.  z = chunk*2 + n.
// part layout: ((chunk*2+n)*OC + oc)*HW + px
// Requires C/split % 16 == 0, HW % 256 == 0.
// ---------------------------------------------------------------------------
__global__ void __launch_bounds__(256, 2)
conv1x1_partial(const float* __restrict__ in, const float* __restrict__ wt,
                float* __restrict__ part, int C, int OC, int HW, int split) {
    int tid = threadIdx.x;
    int px  = blockIdx.x * 256 + tid;
    int oc0 = blockIdx.y * 64;
    int z   = blockIdx.z;
    int n = z & 1, chunk = z >> 1;
    int Cs = C / split;
    int icbeg = chunk * Cs, icend = icbeg + Cs;

    __shared__ __align__(16) float s_in[16 * 256];
    __shared__ __align__(16) float s_w [16 * 64];

    unsigned long long acc[32];
#pragma unroll
    for (int o = 0; o < 32; o++) acc[o] = 0ull;

    const float* inb = in + (size_t)n * C * HW;

    for (int ic0 = icbeg; ic0 < icend; ic0 += 16) {
#pragma unroll
        for (int i = 0; i < 16; i++)
            s_in[i * 256 + tid] = inb[(size_t)(ic0 + i) * HW + px];
        for (int i = tid; i < 16 * 64; i += 256) {
            int oc = i & 63, ic = i >> 6;
            s_w[i] = (oc0 + oc < OC) ? wt[(size_t)(ic0 + ic) * OC + oc0 + oc]
                                     : 0.f;
        }
        __syncthreads();

#pragma unroll 4
        for (int ic = 0; ic < 16; ic++) {
            unsigned long long vv = bcast2(s_in[ic * 256 + tid]);
            const ulonglong2* wp =
                reinterpret_cast<const ulonglong2*>(&s_w[ic * 64]);
#pragma unroll
            for (int o = 0; o < 16; o++) {
                ulonglong2 wv = wp[o];
                fma2(acc[2 * o + 0], vv, wv.x);
                fma2(acc[2 * o + 1], vv, wv.y);
            }
        }
        __syncthreads();
    }

    int nOC = OC - oc0;
    if (nOC > 64) nOC = 64;
    size_t base = ((size_t)(chunk * 2 + n) * OC + oc0) * HW + px;
#pragma unroll
    for (int p = 0; p < 32; p++) {
        float2 f = unpack2(acc[p]);
        if (2 * p + 0 < nOC) part[base + (size_t)(2 * p + 0) * HW] = f.x;
        if (2 * p + 1 < nOC) part[base + (size_t)(2 * p + 1) * HW] = f.y;
    }
}

// ---------------------------------------------------------------------------
// Reduce split-K partials + BN (4,OC stacked g,b,m,v) or bias, optional relu.
// ---------------------------------------------------------------------------
__global__ void reduce_kernel(const float* __restrict__ part,
                              const float* __restrict__ bnp,
                              const float* __restrict__ bias,
                              float* __restrict__ out,
                              int split, int OC, int HW, int relu) {
    int idx = blockIdx.x * 256 + threadIdx.x;
    int total = 2 * OC * HW;
    if (idx >= total) return;
    int oc = (idx / HW) % OC;
    size_t slab = (size_t)2 * OC * HW;
    float s = 0.f;
    for (int c = 0; c < split; c++) s += part[(size_t)c * slab + idx];
    if (bnp) {
        float g = bnp[oc], b = bnp[OC + oc], m = bnp[2 * OC + oc],
              v = bnp[3 * OC + oc];
        float sc = g * rsqrtf(v + 1e-5f);
        s = s * sc + (b - m * sc);
    } else if (bias) {
        s += bias[oc];
    }
    if (relu) s = fmaxf(s, 0.f);
    out[idx] = s;
}

// ---------------------------------------------------------------------------
// Bilinear upsample x2, align_corners=True.  (2,C,h,w) -> (2,C,2h,2w)
// ---------------------------------------------------------------------------
__global__ void upsample2(const float* __restrict__ in, float* __restrict__ out,
                          int C, int h, int w) {
    int H = 2 * h, W = 2 * w;
    int idx = blockIdx.x * 256 + threadIdx.x;
    int total = 2 * C * H * W;
    if (idx >= total) return;
    int x  = idx % W;
    int y  = (idx / W) % H;
    int nc = idx / (W * H);

    float ry = (float)(h - 1) / (float)(H - 1);
    float rx = (float)(w - 1) / (float)(W - 1);
    float fy = y * ry, fx = x * rx;
    int y0 = (int)fy; if (y0 > h - 1) y0 = h - 1;
    int x0 = (int)fx; if (x0 > w - 1) x0 = w - 1;
    int y1 = min(y0 + 1, h - 1);
    int x1 = min(x0 + 1, w - 1);
    float wy = fy - (float)y0;
    float wx = fx - (float)x0;

    const float* p = in + (size_t)nc * h * w;
    float a = p[y0 * w + x0] * (1.f - wy) + p[y1 * w + x0] * wy;
    float b = p[y0 * w + x1] * (1.f - wy) + p[y1 * w + x1] * wy;
    out[idx] = a * (1.f - wx) + b * wx;
}

// ---------------------------------------------------------------------------
// Attention: logits[t] = sum_c q[c,y,x]*k[c,y+dy,x+dx] (zero-pad), softmax(9).
// Parallelized over channel-groups: block 256 = 8 groups x 32 px.
// grid: (HW/32, 2).  Each thread accumulates kd/8 channels; smem tree-reduce.
// ---------------------------------------------------------------------------
__global__ void __launch_bounds__(256, 4)
attn_kernel(const float* __restrict__ q, const float* __restrict__ k,
            float* __restrict__ att, int kd, int H, int W) {
    int lane = threadIdx.x & 31;
    int g    = threadIdx.x >> 5;          // 0..7
    int px   = blockIdx.x * 32 + lane;
    int n    = blockIdx.y;
    int x = px % W, y = px / W;
    size_t HW = (size_t)H * W;
    int cpg = kd >> 3;                    // channels per group

    float a[9];
#pragma unroll
    for (int t = 0; t < 9; t++) a[t] = 0.f;

    const float* qb = q + ((size_t)n * kd + g * cpg) * HW + px;
    const float* kb = k + ((size_t)n * kd + g * cpg) * HW;
    for (int c = 0; c < cpg; c++) {
        float qv = qb[(size_t)c * HW];
        const float* kc = kb + (size_t)c * HW;
#pragma unroll
        for (int t = 0; t < 9; t++) {
            int dy = (t / 3) * 2 - 2, dx = (t % 3) * 2 - 2;
            int yy = y + dy, xx = x + dx;
            if ((unsigned)yy < (unsigned)H && (unsigned)xx < (unsigned)W)
                a[t] += qv * kc[yy * W + xx];
        }
    }

    __shared__ float s[9][8][33];
#pragma unroll
    for (int t = 0; t < 9; t++) s[t][g][lane] = a[t];
    __syncthreads();

    if (g == 0) {
        float b[9];
#pragma unroll
        for (int t = 0; t < 9; t++) {
            float sum = 0.f;
#pragma unroll
            for (int gg = 0; gg < 8; gg++) sum += s[t][gg][lane];
            b[t] = sum;
        }
        float mx = b[0];
#pragma unroll
        for (int t = 1; t < 9; t++) mx = fmaxf(mx, b[t]);
        float sum = 0.f;
#pragma unroll
        for (int t = 0; t < 9; t++) { b[t] = __expf(b[t] - mx); sum += b[t]; }
        float inv = 1.f / sum;
#pragma unroll
        for (int t = 0; t < 9; t++)
            att[((size_t)n * 9 + t) * HW + px] = b[t] * inv;
    }
}

// ---------------------------------------------------------------------------
// Aggregation: out[c,y,x] = sum_t att[t,y,x] * up[c,y+dy,x+dx] (zero-pad).
// grid: (HW/256, C/8, 2); block 256; att tile cached in smem.
// ---------------------------------------------------------------------------
__global__ void agg_kernel(const float* __restrict__ att,
                           const float* __restrict__ up,
                           float* __restrict__ out, int C, int H, int W) {
    int tid = threadIdx.x;
    int px  = blockIdx.x * 256 + tid;
    int c0  = blockIdx.y * 8;
    int n   = blockIdx.z;
    size_t HW = (size_t)H * W;

    __shared__ float s_att[9][256];
#pragma unroll
    for (int t = 0; t < 9; t++)
        s_att[t][tid] = att[((size_t)n * 9 + t) * HW + px];
    __syncthreads();

    int x = px % W, y = px / W;
    const float* upb = up + ((size_t)n * C + c0) * HW;
    float* ob        = out + ((size_t)n * C + c0) * HW;

    for (int c = 0; c < 8; c++) {
        const float* uc = upb + (size_t)c * HW;
        float s = 0.f;
#pragma unroll
        for (int t = 0; t < 9; t++) {
            int dy = (t / 3) * 2 - 2, dx = (t % 3) * 2 - 2;
            int yy = y + dy, xx = x + dx;
            if ((unsigned)yy < (unsigned)H && (unsigned)xx < (unsigned)W)
                s += s_att[t][tid] * uc[yy * W + xx];
        }
        ob[(size_t)c * HW + px] = s;
    }
}

// ---------------------------------------------------------------------------
// Orchestration
// ---------------------------------------------------------------------------
extern "C" void kernel_launch(void* const* d_in, const int* in_sizes, int n_in,
                              void* d_out, int out_size) {
    (void)in_sizes; (void)n_in; (void)out_size;
    const float* c1      = (const float*)d_in[0];
    const float* c2      = (const float*)d_in[1];
    const float* c3      = (const float*)d_in[2];
    const float* c4      = (const float*)d_in[3];
    // c20 (d_in[4]) unused by the math path
    const float* c30     = (const float*)d_in[5];
    const float* c40     = (const float*)d_in[6];
    const float* conv5_w = (const float*)d_in[7];
    const float* bn5     = (const float*)d_in[8];
    const float* conv6_w = (const float*)d_in[9];
    const float* conv6_b = (const float*)d_in[10];
    const float* lu4_w1  = (const float*)d_in[11];
    const float* lu4_bn1 = (const float*)d_in[12];
    const float* lu4_w2  = (const float*)d_in[13];
    const float* lu4_bn2 = (const float*)d_in[14];
    const float* lu3_w1  = (const float*)d_in[15];
    const float* lu3_bn1 = (const float*)d_in[16];
    const float* lu3_w2  = (const float*)d_in[17];
    const float* lu3_bn2 = (const float*)d_in[18];
    const float* lu2_w1  = (const float*)d_in[19];
    const float* lu2_bn1 = (const float*)d_in[20];
    const float* lu2_w2  = (const float*)d_in[21];
    const float* lu2_bn2 = (const float*)d_in[22];

    float *part, *outA, *outB, *up, *q, *k, *klo, *att, *wrep;
    cudaGetSymbolAddress((void**)&part, g_part);
    cudaGetSymbolAddress((void**)&outA, g_outA);
    cudaGetSymbolAddress((void**)&outB, g_outB);
    cudaGetSymbolAddress((void**)&up,   g_up);
    cudaGetSymbolAddress((void**)&q,    g_q);
    cudaGetSymbolAddress((void**)&k,    g_k);
    cudaGetSymbolAddress((void**)&klo,  g_klo);
    cudaGetSymbolAddress((void**)&att,  g_att);
    cudaGetSymbolAddress((void**)&wrep, g_wrep);

    // ---- weight repacks: tiled transposes, fully coalesced both sides ----
    // conv5: (512 rows, 2048*9 cols) -> (ic*9, oc)
    transpose_w<<<dim3((18432 + 31) / 32, 16), 256>>>(conv5_w, wrep + W5_OFF,
                                                      512, 18432);
    transpose_w<<<dim3(32, 4), 256>>>(lu4_w1,  wrep + W_LU4A, 128, 1024);
    transpose_w<<<dim3(64, 4), 256>>>(lu4_w2,  wrep + W_LU4B, 128, 2048);
    transpose_w<<<dim3(16, 2), 256>>>(lu3_w1,  wrep + W_LU3A, 64, 512);
    transpose_w<<<dim3(32, 2), 256>>>(lu3_w2,  wrep + W_LU3B, 64, 1024);
    transpose_w<<<dim3(8,  2), 256>>>(lu2_w1,  wrep + W_LU2A, 64, 256);
    transpose_w<<<dim3(16, 2), 256>>>(lu2_w2,  wrep + W_LU2B, 64, 512);
    transpose_w<<<dim3(16, 1), 256>>>(conv6_w, wrep + W_C6,   19, 512);

    // ---- conv5 + BN + ReLU -> outA (2,512,16,16) ----
    conv5_partial<<<dim3(32, 8, 2), 256>>>(c4, wrep + W5_OFF, part);
    reduce_kernel<<<(2 * 512 * 256) / 256, 256>>>(part, bn5, nullptr, outA,
                                                  32, 512, 256, 1);

    // ---- localUp4: H=W=32, kd=128 ----
    conv1x1_partial<<<dim3(4, 2, 16), 256>>>(c3, wrep + W_LU4A, part, 1024, 128, 1024, 8);
    reduce_kernel<<<(2 * 128 * 1024) / 256, 256>>>(part, lu4_bn1, nullptr, q,
                                                   8, 128, 1024, 0);
    conv1x1_partial<<<dim3(1, 2, 32), 256>>>(c40, wrep + W_LU4B, part, 2048, 128, 256, 16);
    reduce_kernel<<<(2 * 128 * 256) / 256, 256>>>(part, lu4_bn2, nullptr, klo,
                                                  16, 128, 256, 0);
    upsample2<<<(2 * 128 * 1024) / 256, 256>>>(klo, k, 128, 16, 16);
    upsample2<<<(2 * 512 * 1024) / 256, 256>>>(outA, up, 512, 16, 16);
    attn_kernel<<<dim3(32, 2), 256>>>(q, k, att, 128, 32, 32);
    agg_kernel<<<dim3(4, 64, 2), 256>>>(att, up, outB, 512, 32, 32);

    // ---- localUp3: H=W=64, kd=64 ----
    conv1x1_partial<<<dim3(16, 1, 8), 256>>>(c2, wrep + W_LU3A, part, 512, 64, 4096, 4);
    reduce_kernel<<<(2 * 64 * 4096) / 256, 256>>>(part, lu3_bn1, nullptr, q,
                                                  4, 64, 4096, 0);
    conv1x1_partial<<<dim3(4, 1, 16), 256>>>(c30, wrep + W_LU3B, part, 1024, 64, 1024, 8);
    reduce_kernel<<<(2 * 64 * 1024) / 256, 256>>>(part, lu3_bn2, nullptr, klo,
                                                  8, 64, 1024, 0);
    upsample2<<<(2 * 64 * 4096) / 256, 256>>>(klo, k, 64, 32, 32);
    upsample2<<<(2 * 512 * 4096) / 256, 256>>>(outB, up, 512, 32, 32);
    attn_kernel<<<dim3(128, 2), 256>>>(q, k, att, 64, 64, 64);
    agg_kernel<<<dim3(16, 64, 2), 256>>>(att, up, outA, 512, 64, 64);

    // ---- localUp2: H=W=128, kd=64 ----
    conv1x1_partial<<<dim3(64, 1, 4), 256>>>(c1, wrep + W_LU2A, part, 256, 64, 16384, 2);
    reduce_kernel<<<(2 * 64 * 16384) / 256, 256>>>(part, lu2_bn1, nullptr, q,
                                                   2, 64, 16384, 0);
    conv1x1_partial<<<dim3(16, 1, 8), 256>>>(c2, wrep + W_LU2B, part, 512, 64, 4096, 4);
    reduce_kernel<<<(2 * 64 * 4096) / 256, 256>>>(part, lu2_bn2, nullptr, klo,
                                                  4, 64, 4096, 0);
    upsample2<<<(2 * 64 * 16384) / 256, 256>>>(klo, k, 64, 64, 64);
    upsample2<<<(2 * 512 * 16384) / 256, 256>>>(outA, up, 512, 64, 64);
    attn_kernel<<<dim3(512, 2), 256>>>(q, k, att, 64, 128, 128);
    agg_kernel<<<dim3(64, 64, 2), 256>>>(att, up, outB, 512, 128, 128);

    // ---- conv6 (1x1, 512->19) + bias -> d_out (2,19,128,128) ----
    conv1x1_partial<<<dim3(64, 1, 4), 256>>>(outB, wrep + W_C6, part, 512, 19, 16384, 2);
    reduce_kernel<<<(2 * 19 * 16384 + 255) / 256, 256>>>(part, nullptr, conv6_b,
                                                         (float*)d_out,
                                                         2, 19, 16384, 0);
}